// round 5
// baseline (speedup 1.0000x reference)
#include <cuda_runtime.h>

#define H 50
#define BTOT 2048
#define TLEN 1024
#define NB 14          // batches per block
#define NGRP 7         // batch groups per block
#define RB 2           // batches per thread
#define NTH 352        // 50*7 = 350 active, 11 warps -> SMSP load {3,3,3,2}
#define GRID 147       // 147*14 = 2058 >= 2048
#define XCH 16
#define HP 16          // hsh row padded to 16 floats

__device__ float g_h1[BTOT * H];

__device__ __forceinline__ float sigf(float x) {
    return __fdividef(1.0f, 1.0f + __expf(-x));
}
__device__ __forceinline__ float tanh_f(float x) {
    return 1.0f - __fdividef(2.0f, __expf(2.0f * x) + 1.0f);
}

// Layer 1 persistent recurrence.
// Thread (j, bg): all 4 gates of hidden unit j for batches {2bg, 2bg+1} of the
// block's 14. Weights: float4 per (k,j) = 4 gates -> one LDS.128 per k.
// Per-SMSP FMA bound: 3 warps * 8 FFMA/k = 24 instr -> 48 cyc/k.
__global__ void __launch_bounds__(NTH) lstm1_kernel(
    const float* __restrict__ x,
    const float* __restrict__ Wih,
    const float* __restrict__ Whh,
    const float* __restrict__ bih,
    const float* __restrict__ bhh)
{
    __shared__ __align__(16) float4 Wq[H][H];       // [k][j] = (Wi,Wf,Wg,Wo)[j][k]
    __shared__ __align__(16) float hsh[2][H][HP];   // double-buffered h
    __shared__ __align__(16) float xsh[XCH][16];    // x chunk, padded slots

    const int tid = threadIdx.x;
    const bool act = tid < NGRP * H;
    const int bg = tid / H;          // 0..6 (garbage for idle threads, masked)
    const int j  = tid - bg * H;     // 0..49
    const int bbase = blockIdx.x * NB;
    const int sl = bg * RB;          // slot 0,2,...,12

    // Prepack Whh gate quads into shared: Wq[k][j] = 4 gate rows at column k
    for (int i = tid; i < H * H; i += NTH) {
        int k = i / H, jj = i - k * H;
        Wq[k][jj] = make_float4(Whh[jj * H + k],
                                Whh[(H + jj) * H + k],
                                Whh[(2 * H + jj) * H + k],
                                Whh[(3 * H + jj) * H + k]);
    }
    for (int i = tid; i < 2 * H * HP; i += NTH)
        (&hsh[0][0][0])[i] = 0.0f;

    float b0 = 0.f, b1 = 0.f, b2 = 0.f, b3 = 0.f;
    float wi0 = 0.f, wi1 = 0.f, wi2 = 0.f, wi3 = 0.f;
    if (act) {
        b0 = bih[j]         + bhh[j];
        b1 = bih[H + j]     + bhh[H + j];
        b2 = bih[2 * H + j] + bhh[2 * H + j];
        b3 = bih[3 * H + j] + bhh[3 * H + j];
        wi0 = Wih[j]; wi1 = Wih[H + j]; wi2 = Wih[2 * H + j]; wi3 = Wih[3 * H + j];
    }

    float c[RB]  = {0.f, 0.f};
    float hv[RB] = {0.f, 0.f};

    __syncthreads();

    for (int t = 0; t < TLEN; t++) {
        if ((t & (XCH - 1)) == 0) {
            // previous end-of-step barrier covers old xsh reads
            for (int i = tid; i < XCH * NB; i += NTH) {
                int tc = i / NB, s = i - tc * NB;
                int gb = bbase + s;
                // clamp OOB batches of the last block (values unused)
                xsh[tc][s] = x[min(gb, BTOT - 1) * TLEN + t + tc];
            }
            __syncthreads();
        }
        const int buf = t & 1;

        if (act) {
            const float xv0 = xsh[t & (XCH - 1)][sl];
            const float xv1 = xsh[t & (XCH - 1)][sl + 1];
            float a00 = fmaf(xv0, wi0, b0), a01 = fmaf(xv1, wi0, b0);
            float a10 = fmaf(xv0, wi1, b1), a11 = fmaf(xv1, wi1, b1);
            float a20 = fmaf(xv0, wi2, b2), a21 = fmaf(xv1, wi2, b2);
            float a30 = fmaf(xv0, wi3, b3), a31 = fmaf(xv1, wi3, b3);

#pragma unroll
            for (int k = 0; k < H; k++) {
                const float4 w = Wq[k][j];
                const float2 hq = *(const float2*)&hsh[buf][k][sl];
                a00 = fmaf(hq.x, w.x, a00); a01 = fmaf(hq.y, w.x, a01);
                a10 = fmaf(hq.x, w.y, a10); a11 = fmaf(hq.y, w.y, a11);
                a20 = fmaf(hq.x, w.z, a20); a21 = fmaf(hq.y, w.z, a21);
                a30 = fmaf(hq.x, w.w, a30); a31 = fmaf(hq.y, w.w, a31);
            }

            {
                const float ig = sigf(a00), fg = sigf(a10);
                const float gg = tanh_f(a20), og = sigf(a30);
                c[0]  = fmaf(fg, c[0], ig * gg);
                hv[0] = og * tanh_f(c[0]);
            }
            {
                const float ig = sigf(a01), fg = sigf(a11);
                const float gg = tanh_f(a21), og = sigf(a31);
                c[1]  = fmaf(fg, c[1], ig * gg);
                hv[1] = og * tanh_f(c[1]);
            }
            *(float2*)&hsh[buf ^ 1][j][sl] = make_float2(hv[0], hv[1]);
        }
        __syncthreads();
    }

    if (act) {
#pragma unroll
        for (int r = 0; r < RB; r++) {
            int gb = bbase + sl + r;
            if (gb < BTOT) g_h1[gb * H + j] = hv[r];
        }
    }
}

#define NTH2 256
#define BT2 16

__global__ void __launch_bounds__(NTH2) lstm2_fc_kernel(
    const float* __restrict__ W2ih,
    const float* __restrict__ b2ih,
    const float* __restrict__ b2hh,
    const float* __restrict__ fcW,
    const float* __restrict__ fcb,
    float* __restrict__ out)
{
    __shared__ __align__(16) float Wsh[H][4 * H];
    __shared__ __align__(16) float h1sh[H][BT2];
    __shared__ float h2sh[BT2][H];

    const int tid = threadIdx.x;
    const int j = tid & 63;
    const int bg = tid >> 6;
    const int bbase = blockIdx.x * BT2;
    const int bloc = bg * 4;

    for (int i = tid; i < 4 * H * H; i += NTH2) {
        int g = i / H, k = i - g * H;
        Wsh[k][g] = W2ih[i];
    }
    for (int i = tid; i < H * BT2; i += NTH2) {
        int k = i >> 4, bl = i & 15;
        h1sh[k][bl] = g_h1[(bbase + bl) * H + k];
    }
    __syncthreads();

    if (j < H) {
        const float bias0 = b2ih[j]         + b2hh[j];
        const float bias2 = b2ih[2 * H + j] + b2hh[2 * H + j];
        const float bias3 = b2ih[3 * H + j] + b2hh[3 * H + j];
        float a0[4], a2[4], a3[4];
#pragma unroll
        for (int r = 0; r < 4; r++) { a0[r] = bias0; a2[r] = bias2; a3[r] = bias3; }
#pragma unroll
        for (int k = 0; k < H; k++) {
            const float w0 = Wsh[k][j];
            const float w2 = Wsh[k][2 * H + j];
            const float w3 = Wsh[k][3 * H + j];
            const float4 h4 = *(const float4*)&h1sh[k][bloc];
            const float hr[4] = {h4.x, h4.y, h4.z, h4.w};
#pragma unroll
            for (int r = 0; r < 4; r++) {
                a0[r] = fmaf(hr[r], w0, a0[r]);
                a2[r] = fmaf(hr[r], w2, a2[r]);
                a3[r] = fmaf(hr[r], w3, a3[r]);
            }
        }
#pragma unroll
        for (int r = 0; r < 4; r++) {
            const float ig = sigf(a0[r]);           // f-gate unused: c0 = 0
            const float gg = tanh_f(a2[r]);
            const float og = sigf(a3[r]);
            const float cc = ig * gg;
            h2sh[bloc + r][j] = og * tanh_f(cc);
        }
    }
    __syncthreads();

    if (tid < BT2) {
        float s = fcb[0];
#pragma unroll
        for (int k = 0; k < H; k++)
            s = fmaf(h2sh[tid][k], fcW[k], s);
        out[bbase + tid] = s;
    }
}

extern "C" void kernel_launch(void* const* d_in, const int* in_sizes, int n_in,
                              void* d_out, int out_size)
{
    const float* x     = (const float*)d_in[0];
    const float* w1ih  = (const float*)d_in[1];
    const float* w1hh  = (const float*)d_in[2];
    const float* b1ih  = (const float*)d_in[3];
    const float* b1hh  = (const float*)d_in[4];
    const float* w2ih  = (const float*)d_in[5];
    // d_in[6] = lstm2_Whh: unused (layer-2 initial state is zero)
    const float* b2ih  = (const float*)d_in[7];
    const float* b2hh  = (const float*)d_in[8];
    const float* fcW   = (const float*)d_in[9];
    const float* fcb   = (const float*)d_in[10];
    float* out = (float*)d_out;

    lstm1_kernel<<<GRID, NTH>>>(x, w1ih, w1hh, b1ih, b1hh);
    lstm2_fc_kernel<<<BTOT / BT2, NTH2>>>(w2ih, b2ih, b2hh, fcW, fcb, out);
}

// round 6
// speedup vs baseline: 1.0011x; 1.0011x over previous
#include <cuda_runtime.h>

#define H 50
#define BTOT 2048
#define TLEN 1024
#define NB 14          // batches per block
#define NGRP 7         // batch groups per block
#define RB 2           // batches per thread
#define NTH 352        // 50*7 = 350 active, 11 warps -> SMSP load {3,3,3,2}
#define GRID 147       // 147*14 = 2058 >= 2048
#define XCH 16
#define HP 16          // hsh row padded to 16 floats

__device__ float g_h1[BTOT * H];

__device__ __forceinline__ float sigf(float x) {
    return __fdividef(1.0f, 1.0f + __expf(-x));
}
__device__ __forceinline__ float tanh_f(float x) {
    return 1.0f - __fdividef(2.0f, __expf(2.0f * x) + 1.0f);
}

// Layer 1 persistent recurrence.
// Thread (j, bg): all 4 gates of hidden unit j for batches {2bg, 2bg+1} of the
// block's 14. Weights: float4 per (k,j) = 4 gates -> one LDS.128 per k.
// Per-SMSP FMA bound: 3 warps * 8 FFMA/k = 24 instr -> 48 cyc/k.
__global__ void __launch_bounds__(NTH) lstm1_kernel(
    const float* __restrict__ x,
    const float* __restrict__ Wih,
    const float* __restrict__ Whh,
    const float* __restrict__ bih,
    const float* __restrict__ bhh)
{
    __shared__ __align__(16) float4 Wq[H][H];       // [k][j] = (Wi,Wf,Wg,Wo)[j][k]
    __shared__ __align__(16) float hsh[2][H][HP];   // double-buffered h
    __shared__ __align__(16) float xsh[XCH][16];    // x chunk, padded slots

    const int tid = threadIdx.x;
    const bool act = tid < NGRP * H;
    const int bg = tid / H;          // 0..6 (garbage for idle threads, masked)
    const int j  = tid - bg * H;     // 0..49
    const int bbase = blockIdx.x * NB;
    const int sl = bg * RB;          // slot 0,2,...,12

    // Prepack Whh gate quads into shared: Wq[k][j] = 4 gate rows at column k
    for (int i = tid; i < H * H; i += NTH) {
        int k = i / H, jj = i - k * H;
        Wq[k][jj] = make_float4(Whh[jj * H + k],
                                Whh[(H + jj) * H + k],
                                Whh[(2 * H + jj) * H + k],
                                Whh[(3 * H + jj) * H + k]);
    }
    for (int i = tid; i < 2 * H * HP; i += NTH)
        (&hsh[0][0][0])[i] = 0.0f;

    float b0 = 0.f, b1 = 0.f, b2 = 0.f, b3 = 0.f;
    float wi0 = 0.f, wi1 = 0.f, wi2 = 0.f, wi3 = 0.f;
    if (act) {
        b0 = bih[j]         + bhh[j];
        b1 = bih[H + j]     + bhh[H + j];
        b2 = bih[2 * H + j] + bhh[2 * H + j];
        b3 = bih[3 * H + j] + bhh[3 * H + j];
        wi0 = Wih[j]; wi1 = Wih[H + j]; wi2 = Wih[2 * H + j]; wi3 = Wih[3 * H + j];
    }

    float c[RB]  = {0.f, 0.f};
    float hv[RB] = {0.f, 0.f};

    __syncthreads();

    for (int t = 0; t < TLEN; t++) {
        if ((t & (XCH - 1)) == 0) {
            // previous end-of-step barrier covers old xsh reads
            for (int i = tid; i < XCH * NB; i += NTH) {
                int tc = i / NB, s = i - tc * NB;
                int gb = bbase + s;
                // clamp OOB batches of the last block (values unused)
                xsh[tc][s] = x[min(gb, BTOT - 1) * TLEN + t + tc];
            }
            __syncthreads();
        }
        const int buf = t & 1;

        if (act) {
            const float xv0 = xsh[t & (XCH - 1)][sl];
            const float xv1 = xsh[t & (XCH - 1)][sl + 1];
            float a00 = fmaf(xv0, wi0, b0), a01 = fmaf(xv1, wi0, b0);
            float a10 = fmaf(xv0, wi1, b1), a11 = fmaf(xv1, wi1, b1);
            float a20 = fmaf(xv0, wi2, b2), a21 = fmaf(xv1, wi2, b2);
            float a30 = fmaf(xv0, wi3, b3), a31 = fmaf(xv1, wi3, b3);

#pragma unroll
            for (int k = 0; k < H; k++) {
                const float4 w = Wq[k][j];
                const float2 hq = *(const float2*)&hsh[buf][k][sl];
                a00 = fmaf(hq.x, w.x, a00); a01 = fmaf(hq.y, w.x, a01);
                a10 = fmaf(hq.x, w.y, a10); a11 = fmaf(hq.y, w.y, a11);
                a20 = fmaf(hq.x, w.z, a20); a21 = fmaf(hq.y, w.z, a21);
                a30 = fmaf(hq.x, w.w, a30); a31 = fmaf(hq.y, w.w, a31);
            }

            {
                const float ig = sigf(a00), fg = sigf(a10);
                const float gg = tanh_f(a20), og = sigf(a30);
                c[0]  = fmaf(fg, c[0], ig * gg);
                hv[0] = og * tanh_f(c[0]);
            }
            {
                const float ig = sigf(a01), fg = sigf(a11);
                const float gg = tanh_f(a21), og = sigf(a31);
                c[1]  = fmaf(fg, c[1], ig * gg);
                hv[1] = og * tanh_f(c[1]);
            }
            *(float2*)&hsh[buf ^ 1][j][sl] = make_float2(hv[0], hv[1]);
        }
        __syncthreads();
    }

    if (act) {
#pragma unroll
        for (int r = 0; r < RB; r++) {
            int gb = bbase + sl + r;
            if (gb < BTOT) g_h1[gb * H + j] = hv[r];
        }
    }
}

#define NTH2 256
#define BT2 16

__global__ void __launch_bounds__(NTH2) lstm2_fc_kernel(
    const float* __restrict__ W2ih,
    const float* __restrict__ b2ih,
    const float* __restrict__ b2hh,
    const float* __restrict__ fcW,
    const float* __restrict__ fcb,
    float* __restrict__ out)
{
    __shared__ __align__(16) float Wsh[H][4 * H];
    __shared__ __align__(16) float h1sh[H][BT2];
    __shared__ float h2sh[BT2][H];

    const int tid = threadIdx.x;
    const int j = tid & 63;
    const int bg = tid >> 6;
    const int bbase = blockIdx.x * BT2;
    const int bloc = bg * 4;

    for (int i = tid; i < 4 * H * H; i += NTH2) {
        int g = i / H, k = i - g * H;
        Wsh[k][g] = W2ih[i];
    }
    for (int i = tid; i < H * BT2; i += NTH2) {
        int k = i >> 4, bl = i & 15;
        h1sh[k][bl] = g_h1[(bbase + bl) * H + k];
    }
    __syncthreads();

    if (j < H) {
        const float bias0 = b2ih[j]         + b2hh[j];
        const float bias2 = b2ih[2 * H + j] + b2hh[2 * H + j];
        const float bias3 = b2ih[3 * H + j] + b2hh[3 * H + j];
        float a0[4], a2[4], a3[4];
#pragma unroll
        for (int r = 0; r < 4; r++) { a0[r] = bias0; a2[r] = bias2; a3[r] = bias3; }
#pragma unroll
        for (int k = 0; k < H; k++) {
            const float w0 = Wsh[k][j];
            const float w2 = Wsh[k][2 * H + j];
            const float w3 = Wsh[k][3 * H + j];
            const float4 h4 = *(const float4*)&h1sh[k][bloc];
            const float hr[4] = {h4.x, h4.y, h4.z, h4.w};
#pragma unroll
            for (int r = 0; r < 4; r++) {
                a0[r] = fmaf(hr[r], w0, a0[r]);
                a2[r] = fmaf(hr[r], w2, a2[r]);
                a3[r] = fmaf(hr[r], w3, a3[r]);
            }
        }
#pragma unroll
        for (int r = 0; r < 4; r++) {
            const float ig = sigf(a0[r]);           // f-gate unused: c0 = 0
            const float gg = tanh_f(a2[r]);
            const float og = sigf(a3[r]);
            const float cc = ig * gg;
            h2sh[bloc + r][j] = og * tanh_f(cc);
        }
    }
    __syncthreads();

    if (tid < BT2) {
        float s = fcb[0];
#pragma unroll
        for (int k = 0; k < H; k++)
            s = fmaf(h2sh[tid][k], fcW[k], s);
        out[bbase + tid] = s;
    }
}

extern "C" void kernel_launch(void* const* d_in, const int* in_sizes, int n_in,
                              void* d_out, int out_size)
{
    const float* x     = (const float*)d_in[0];
    const float* w1ih  = (const float*)d_in[1];
    const float* w1hh  = (const float*)d_in[2];
    const float* b1ih  = (const float*)d_in[3];
    const float* b1hh  = (const float*)d_in[4];
    const float* w2ih  = (const float*)d_in[5];
    // d_in[6] = lstm2_Whh: unused (layer-2 initial state is zero)
    const float* b2ih  = (const float*)d_in[7];
    const float* b2hh  = (const float*)d_in[8];
    const float* fcW   = (const float*)d_in[9];
    const float* fcb   = (const float*)d_in[10];
    float* out = (float*)d_out;

    lstm1_kernel<<<GRID, NTH>>>(x, w1ih, w1hh, b1ih, b1hh);
    lstm2_fc_kernel<<<BTOT / BT2, NTH2>>>(w2ih, b2ih, b2hh, fcW, fcb, out);
}

// round 7
// speedup vs baseline: 1.2860x; 1.2846x over previous
#include <cuda_runtime.h>

#define H 50
#define BTOT 2048
#define TLEN 1024
#define BTILE 16
#define NTH 200
#define XCH 16
#define HP 20   // padded hsh row: 80B = odd multiple of 16B -> conflict-free strided 16B access

__device__ float g_h1[BTOT * H];

typedef unsigned long long u64;

__device__ __forceinline__ void ffma2(u64 &d, u64 a, u64 b) {
    asm("fma.rn.f32x2 %0, %1, %2, %0;" : "+l"(d) : "l"(a), "l"(b));
}
__device__ __forceinline__ u64 pack2(float lo, float hi) {
    u64 r; asm("mov.b64 %0, {%1, %2};" : "=l"(r) : "f"(lo), "f"(hi)); return r;
}
__device__ __forceinline__ u64 splat2(float x) {
    u64 r; asm("mov.b64 %0, {%1, %1};" : "=l"(r) : "f"(x)); return r;
}
__device__ __forceinline__ void unpack2(u64 v, float &lo, float &hi) {
    asm("mov.b64 {%0, %1}, %2;" : "=f"(lo), "=f"(hi) : "l"(v));
}

// Single-MUFU activations (tanh.approx.f32, sm_75+).
__device__ __forceinline__ float tanh_f(float x) {
    float y; asm("tanh.approx.f32 %0, %1;" : "=f"(y) : "f"(x)); return y;
}
__device__ __forceinline__ float sigf(float x) {
    return fmaf(0.5f, tanh_f(0.5f * x), 0.5f);
}

// Layer 1: persistent recurrence. Block = 200 threads = 4 batch-groups x 50 hidden.
// Thread (j, bg) computes all 4 gates for hidden unit j, batches bloc..bloc+3.
// Gates packed in f32x2 pairs: acc0 = (i_pre, f_pre), acc1 = (g_pre, o_pre).
__global__ void __launch_bounds__(NTH) lstm1_kernel(
    const float* __restrict__ x,
    const float* __restrict__ Wih,
    const float* __restrict__ Whh,
    const float* __restrict__ bih,
    const float* __restrict__ bhh)
{
    __shared__ __align__(16) float2 Wp0[H][H];       // [k][j] = (W_i[j][k], W_f[j][k])
    __shared__ __align__(16) float2 Wp1[H][H];       // [k][j] = (W_g[j][k], W_o[j][k])
    __shared__ __align__(16) float hsh[2][H][HP];    // double-buffered h, padded rows
    __shared__ __align__(16) float xsh[XCH][BTILE];  // x chunk

    const int tid = threadIdx.x;
    const int bg = tid / H;          // 0..3
    const int j  = tid - bg * H;     // 0..49, every thread active
    const int bbase = blockIdx.x * BTILE;
    const int bloc = bg * 4;

    // Prepack Whh gate-pairs into shared.
    for (int i = tid; i < 2 * H * H; i += NTH) {
        int p = i / (H * H);
        int rem = i - p * H * H;
        int k  = rem / H;
        int jj = rem - k * H;
        float lo = Whh[(p * 2 * H + jj) * H + k];
        float hi = Whh[(p * 2 * H + H + jj) * H + k];
        if (p) Wp1[k][jj] = make_float2(lo, hi);
        else   Wp0[k][jj] = make_float2(lo, hi);
    }
    for (int i = tid; i < 2 * H * HP; i += NTH)
        (&hsh[0][0][0])[i] = 0.0f;

    const u64 biasp0 = pack2(bih[j] + bhh[j],                 bih[H + j] + bhh[H + j]);
    const u64 biasp1 = pack2(bih[2 * H + j] + bhh[2 * H + j], bih[3 * H + j] + bhh[3 * H + j]);
    const u64 wip0 = pack2(Wih[j],         Wih[H + j]);
    const u64 wip1 = pack2(Wih[2 * H + j], Wih[3 * H + j]);

    float c[4]  = {0.f, 0.f, 0.f, 0.f};
    float hv[4] = {0.f, 0.f, 0.f, 0.f};

    __syncthreads();

    for (int t = 0; t < TLEN; t++) {
        if ((t & (XCH - 1)) == 0) {
            // previous end-of-step barrier guarantees old xsh reads are done
            for (int i = tid; i < XCH * BTILE; i += NTH) {
                int tc = i >> 4, bl = i & 15;
                xsh[tc][bl] = x[(bbase + bl) * TLEN + t + tc];
            }
            __syncthreads();
        }
        const int buf = t & 1;

        const float4 xq = *(const float4*)&xsh[t & (XCH - 1)][bloc];
        u64 xs[4] = {splat2(xq.x), splat2(xq.y), splat2(xq.z), splat2(xq.w)};

        u64 a0[4], a1[4];
#pragma unroll
        for (int r = 0; r < 4; r++) {
            a0[r] = biasp0; a1[r] = biasp1;
            ffma2(a0[r], xs[r], wip0);
            ffma2(a1[r], xs[r], wip1);
        }

#pragma unroll
        for (int k = 0; k < H; k++) {
            const u64 w0 = *(const u64*)&Wp0[k][j];
            const u64 w1 = *(const u64*)&Wp1[k][j];
            const float4 hq = *(const float4*)&hsh[buf][k][bloc];
            const u64 hs0 = splat2(hq.x), hs1 = splat2(hq.y),
                      hs2 = splat2(hq.z), hs3 = splat2(hq.w);
            ffma2(a0[0], hs0, w0); ffma2(a1[0], hs0, w1);
            ffma2(a0[1], hs1, w0); ffma2(a1[1], hs1, w1);
            ffma2(a0[2], hs2, w0); ffma2(a1[2], hs2, w1);
            ffma2(a0[3], hs3, w0); ffma2(a1[3], hs3, w1);
        }

#pragma unroll
        for (int r = 0; r < 4; r++) {
            float ip, fp, gp, op;
            unpack2(a0[r], ip, fp);
            unpack2(a1[r], gp, op);
            const float ig = sigf(ip);
            const float fg = sigf(fp);
            const float gg = tanh_f(gp);
            const float og = sigf(op);
            c[r]  = fmaf(fg, c[r], ig * gg);
            hv[r] = og * tanh_f(c[r]);
        }
        *(float4*)&hsh[buf ^ 1][j][bloc] = make_float4(hv[0], hv[1], hv[2], hv[3]);
        __syncthreads();
    }

#pragma unroll
    for (int r = 0; r < 4; r++)
        g_h1[(bbase + bloc + r) * H + j] = hv[r];
}

#define NTH2 256

__global__ void __launch_bounds__(NTH2) lstm2_fc_kernel(
    const float* __restrict__ W2ih,
    const float* __restrict__ b2ih,
    const float* __restrict__ b2hh,
    const float* __restrict__ fcW,
    const float* __restrict__ fcb,
    float* __restrict__ out)
{
    __shared__ __align__(16) float Wsh[H][4 * H];
    __shared__ __align__(16) float h1sh[H][BTILE];
    __shared__ float h2sh[BTILE][H];

    const int tid = threadIdx.x;
    const int j = tid & 63;
    const int bg = tid >> 6;
    const int bbase = blockIdx.x * BTILE;
    const int bloc = bg * 4;

    for (int i = tid; i < 4 * H * H; i += NTH2) {
        int g = i / H, k = i - g * H;
        Wsh[k][g] = W2ih[i];
    }
    for (int i = tid; i < H * BTILE; i += NTH2) {
        int k = i >> 4, bl = i & 15;
        h1sh[k][bl] = g_h1[(bbase + bl) * H + k];
    }
    __syncthreads();

    if (j < H) {
        const float bias0 = b2ih[j]         + b2hh[j];
        const float bias2 = b2ih[2 * H + j] + b2hh[2 * H + j];
        const float bias3 = b2ih[3 * H + j] + b2hh[3 * H + j];
        float a0[4], a2[4], a3[4];
#pragma unroll
        for (int r = 0; r < 4; r++) { a0[r] = bias0; a2[r] = bias2; a3[r] = bias3; }
#pragma unroll
        for (int k = 0; k < H; k++) {
            const float w0 = Wsh[k][j];
            const float w2 = Wsh[k][2 * H + j];
            const float w3 = Wsh[k][3 * H + j];
            const float4 h4 = *(const float4*)&h1sh[k][bloc];
            const float hr[4] = {h4.x, h4.y, h4.z, h4.w};
#pragma unroll
            for (int r = 0; r < 4; r++) {
                a0[r] = fmaf(hr[r], w0, a0[r]);
                a2[r] = fmaf(hr[r], w2, a2[r]);
                a3[r] = fmaf(hr[r], w3, a3[r]);
            }
        }
#pragma unroll
        for (int r = 0; r < 4; r++) {
            const float ig = sigf(a0[r]);           // f-gate unused: c0 = 0
            const float gg = tanh_f(a2[r]);
            const float og = sigf(a3[r]);
            const float cc = ig * gg;
            h2sh[bloc + r][j] = og * tanh_f(cc);
        }
    }
    __syncthreads();

    if (tid < BTILE) {
        float s = fcb[0];
#pragma unroll
        for (int k = 0; k < H; k++)
            s = fmaf(h2sh[tid][k], fcW[k], s);
        out[bbase + tid] = s;
    }
}

extern "C" void kernel_launch(void* const* d_in, const int* in_sizes, int n_in,
                              void* d_out, int out_size)
{
    const float* x     = (const float*)d_in[0];
    const float* w1ih  = (const float*)d_in[1];
    const float* w1hh  = (const float*)d_in[2];
    const float* b1ih  = (const float*)d_in[3];
    const float* b1hh  = (const float*)d_in[4];
    const float* w2ih  = (const float*)d_in[5];
    // d_in[6] = lstm2_Whh: unused (layer-2 initial state is zero)
    const float* b2ih  = (const float*)d_in[7];
    const float* b2hh  = (const float*)d_in[8];
    const float* fcW   = (const float*)d_in[9];
    const float* fcb   = (const float*)d_in[10];
    float* out = (float*)d_out;

    lstm1_kernel<<<BTOT / BTILE, NTH>>>(x, w1ih, w1hh, b1ih, b1hh);
    lstm2_fc_kernel<<<BTOT / BTILE, NTH2>>>(w2ih, b2ih, b2hh, fcW, fcb, out);
}